// round 3
// baseline (speedup 1.0000x reference)
#include <cuda_runtime.h>
#include <cuda_bf16.h>
#include <stdint.h>

// Problem constants
#define N_ROWS 4096
#define C_CLS  1000
#define D_DIM  1024
#define NC_PER_T 4096000u          // N*C
#define SIG_OFF  4096000           // sigma offset in d_out (after mu_out)

// mu scratch (sigma lives in d_out directly)
__device__ float g_mu[N_ROWS * C_CLS];

// ---------------------------------------------------------------------------
// Threefry2x32-20, key (0, 42) == jax.random.key(42), PARTITIONABLE mode:
// element i uses counter pair (u32(i>>32)=0, u32(i)); 32-bit output is the
// xor-fold of the two output lanes.
// ---------------------------------------------------------------------------
__device__ __forceinline__ uint32_t tf_fold(uint32_t ctr) {
    const uint32_t ks0 = 0u;
    const uint32_t ks1 = 42u;
    const uint32_t ks2 = 0x1BD11BDAu ^ 0u ^ 42u;
    uint32_t x0 = 0u + ks0;
    uint32_t x1 = ctr + ks1;
#define TFR(r) { x0 += x1; x1 = __funnelshift_l(x1, x1, (r)); x1 ^= x0; }
    TFR(13) TFR(15) TFR(26) TFR(6)
    x0 += ks1; x1 += ks2 + 1u;
    TFR(17) TFR(29) TFR(16) TFR(24)
    x0 += ks2; x1 += ks0 + 2u;
    TFR(13) TFR(15) TFR(26) TFR(6)
    x0 += ks0; x1 += ks1 + 3u;
    TFR(17) TFR(29) TFR(16) TFR(24)
    x0 += ks1; x1 += ks2 + 4u;
    TFR(13) TFR(15) TFR(26) TFR(6)
    x0 += ks2; x1 += ks0 + 5u;
#undef TFR
    return x0 ^ x1;
}

// bits -> uniform(-0.99999994, 1) -> sqrt(2)*erfinv(u)   (matches jax.random.normal)
__device__ __forceinline__ float bits_to_normal(uint32_t b) {
    float f = __uint_as_float((b >> 9) | 0x3f800000u) - 1.0f;   // [0,1)
    float u = fmaf(f, 2.0f, -0.99999994f);   // exact: *2 is exact, single add
    u = fmaxf(u, -0.99999994f);
    return 1.41421356f * erfinvf(u);
}

// ---------------------------------------------------------------------------
// Kernel A: SGEMM h = x @ W^T, with fused epilogue:
//   j <  1000 : g_mu[n][j]   = h
//   j >= 1000 : out_sigma[n][j-1000] = exp(0.5*h)
// 128x128x16 tile, 256 threads, 8x8 per-thread microtile.
// ---------------------------------------------------------------------------
__global__ __launch_bounds__(256) void gemm_kernel(
    const float* __restrict__ X, const float* __restrict__ W,
    float* __restrict__ out)
{
    __shared__ float As[16][128];
    __shared__ float Bs[16][128];

    const int bm = blockIdx.y * 128;        // n tile
    const int bn = blockIdx.x * 128;        // j tile (0..2047)
    const int tid = threadIdx.x;
    const int tm = (tid >> 4) << 3;
    const int tn = (tid & 15) << 3;
    const int lr = tid >> 2;                // loader row 0..63
    const int lk = (tid & 3) << 2;          // loader k 0,4,8,12

    float acc[8][8];
#pragma unroll
    for (int i = 0; i < 8; ++i)
#pragma unroll
        for (int j = 0; j < 8; ++j) acc[i][j] = 0.f;

    for (int k0 = 0; k0 < D_DIM; k0 += 16) {
        float4 a0 = *(const float4*)(X + (size_t)(bm + lr) * D_DIM + k0 + lk);
        float4 a1 = *(const float4*)(X + (size_t)(bm + lr + 64) * D_DIM + k0 + lk);
        float4 b0 = make_float4(0.f, 0.f, 0.f, 0.f);
        float4 b1 = make_float4(0.f, 0.f, 0.f, 0.f);
        if (bn + lr < 2000)
            b0 = *(const float4*)(W + (size_t)(bn + lr) * D_DIM + k0 + lk);
        if (bn + lr + 64 < 2000)
            b1 = *(const float4*)(W + (size_t)(bn + lr + 64) * D_DIM + k0 + lk);

        __syncthreads();
        As[lk + 0][lr] = a0.x; As[lk + 1][lr] = a0.y;
        As[lk + 2][lr] = a0.z; As[lk + 3][lr] = a0.w;
        As[lk + 0][lr + 64] = a1.x; As[lk + 1][lr + 64] = a1.y;
        As[lk + 2][lr + 64] = a1.z; As[lk + 3][lr + 64] = a1.w;
        Bs[lk + 0][lr] = b0.x; Bs[lk + 1][lr] = b0.y;
        Bs[lk + 2][lr] = b0.z; Bs[lk + 3][lr] = b0.w;
        Bs[lk + 0][lr + 64] = b1.x; Bs[lk + 1][lr + 64] = b1.y;
        Bs[lk + 2][lr + 64] = b1.z; Bs[lk + 3][lr + 64] = b1.w;
        __syncthreads();

#pragma unroll
        for (int k = 0; k < 16; ++k) {
            float4 av0 = *(const float4*)&As[k][tm];
            float4 av1 = *(const float4*)&As[k][tm + 4];
            float4 bv0 = *(const float4*)&Bs[k][tn];
            float4 bv1 = *(const float4*)&Bs[k][tn + 4];
            float ar[8] = {av0.x, av0.y, av0.z, av0.w, av1.x, av1.y, av1.z, av1.w};
            float br[8] = {bv0.x, bv0.y, bv0.z, bv0.w, bv1.x, bv1.y, bv1.z, bv1.w};
#pragma unroll
            for (int i = 0; i < 8; ++i)
#pragma unroll
                for (int j = 0; j < 8; ++j)
                    acc[i][j] = fmaf(ar[i], br[j], acc[i][j]);
        }
    }

#pragma unroll
    for (int i = 0; i < 8; ++i) {
        const int n = bm + tm + i;
#pragma unroll
        for (int j8 = 0; j8 < 8; ++j8) {
            const int j = bn + tn + j8;
            const float v = acc[i][j8];
            if (j < 1000) {
                g_mu[(size_t)n * C_CLS + j] = v;
            } else if (j < 2000) {
                out[SIG_OFF + (size_t)n * C_CLS + (j - 1000)] = __expf(0.5f * v);
            }
        }
    }
}

// ---------------------------------------------------------------------------
// Kernel B: per-n sampling + softmax + mean + exp, fully register-resident.
// One CTA per n. 256 threads, 4 classes each. Each iteration handles the
// t-pair (tp, tp+16) (arbitrary pairing; every element is an independent
// hash in partitionable mode). Block-reduce the two per-t sums, normalize,
// accumulate. Double-buffered wsum -> one __syncthreads per iteration.
// ---------------------------------------------------------------------------
__global__ __launch_bounds__(256) void sample_kernel(float* __restrict__ out)
{
    __shared__ float wsum[2][2][8];   // [buf][pair 0/1][warp]

    const int n = blockIdx.x;
    const int tid = threadIdx.x;
    const int warp = tid >> 5;
    const int lane = tid & 31;
    const int c0 = tid << 2;
    const bool active = (c0 < C_CLS);
    const float* g_sigma = out + SIG_OFF;

    float mu[4] = {0.f, 0.f, 0.f, 0.f};
    float sg[4] = {0.f, 0.f, 0.f, 0.f};
    if (active) {
        float4 m4 = *(const float4*)(g_mu + (size_t)n * C_CLS + c0);
        float4 s4 = *(const float4*)(g_sigma + (size_t)n * C_CLS + c0);
        mu[0] = m4.x; mu[1] = m4.y; mu[2] = m4.z; mu[3] = m4.w;
        sg[0] = s4.x; sg[1] = s4.y; sg[2] = s4.z; sg[3] = s4.w;
    }

    float a0 = 0.f, a1 = 0.f, a2 = 0.f, a3 = 0.f;

#pragma unroll 1
    for (int tp = 0; tp < 16; ++tp) {
        const int buf = tp & 1;
        float q0[4], q1[4];
        float s0 = 0.f, s1 = 0.f;
        if (active) {
            const uint32_t ib = (uint32_t)tp * NC_PER_T + (uint32_t)n * 1000u + (uint32_t)c0;
#pragma unroll
            for (int j = 0; j < 4; ++j) {
                uint32_t b0 = tf_fold(ib + j);                      // t = tp
                uint32_t b1 = tf_fold(ib + j + 16u * NC_PER_T);     // t = tp+16
                float e0 = bits_to_normal(b0);
                float e1 = bits_to_normal(b1);
                q0[j] = __expf(fmaf(sg[j], e0, mu[j]));
                q1[j] = __expf(fmaf(sg[j], e1, mu[j]));
                s0 += q0[j]; s1 += q1[j];
            }
        } else {
#pragma unroll
            for (int j = 0; j < 4; ++j) { q0[j] = 0.f; q1[j] = 0.f; }
        }
#pragma unroll
        for (int off = 16; off; off >>= 1) {
            s0 += __shfl_xor_sync(0xffffffffu, s0, off);
            s1 += __shfl_xor_sync(0xffffffffu, s1, off);
        }
        if (lane == 0) {
            wsum[buf][0][warp] = s0;
            wsum[buf][1][warp] = s1;
        }
        __syncthreads();

        float t0 = 0.f, t1 = 0.f;
#pragma unroll
        for (int w = 0; w < 8; ++w) {
            t0 += wsum[buf][0][w];
            t1 += wsum[buf][1][w];
        }
        const float inv0 = __frcp_rn(t0);
        const float inv1 = __frcp_rn(t1);

        a0 = fmaf(q0[0], inv0, a0); a0 = fmaf(q1[0], inv1, a0);
        a1 = fmaf(q0[1], inv0, a1); a1 = fmaf(q1[1], inv1, a1);
        a2 = fmaf(q0[2], inv0, a2); a2 = fmaf(q1[2], inv1, a2);
        a3 = fmaf(q0[3], inv0, a3); a3 = fmaf(q1[3], inv1, a3);
    }

    if (active) {
        float4 o;
        o.x = __expf(a0 * 0.03125f);
        o.y = __expf(a1 * 0.03125f);
        o.z = __expf(a2 * 0.03125f);
        o.w = __expf(a3 * 0.03125f);
        *(float4*)(out + (size_t)n * C_CLS + c0) = o;
    }
}

// ---------------------------------------------------------------------------
extern "C" void kernel_launch(void* const* d_in, const int* in_sizes, int n_in,
                              void* d_out, int out_size)
{
    const float* X = (const float*)d_in[0];   // (4096, 1024)
    const float* W = (const float*)d_in[1];   // (2000, 1024)
    float* out = (float*)d_out;               // mu_out (4096,1000) ++ sigma (4096,1000)

    gemm_kernel<<<dim3(16, 32), 256>>>(X, W, out);
    sample_kernel<<<N_ROWS, 256>>>(out);
}